// round 2
// baseline (speedup 1.0000x reference)
#include <cuda_runtime.h>
#include <stdint.h>

#define F_IN 128
#define D1   64
#define H1   8
#define C2   40
#define NMAX 100352
#define MMAX 1703936   // E + N upper bound

// ---------------- scratch (static device allocations) ----------------
__device__ __align__(16) float g_h1 [NMAX * D1];   // layer1 features h = x@W1
__device__ __align__(16) float g_hm [NMAX * D1];   // elu(agg1)+b1  (layer2 input)
__device__ __align__(16) float g_a1s[NMAX * H1];
__device__ __align__(16) float g_a1d[NMAX * H1];
__device__ __align__(16) float g_h2 [NMAX * C2];
__device__ __align__(16) float g_a2s[NMAX];
__device__ __align__(16) float g_a2d[NMAX];
__device__ __align__(16) int   g_deg[NMAX];
__device__ __align__(16) int   g_cur[NMAX];
__device__ __align__(16) int   g_row[NMAX + 1];
__device__ __align__(16) int   g_bsum[256];
__device__ __align__(16) int   g_csr[MMAX];
__device__ int g_is32;   // 1 if edge_index is int32, 0 if int64

// ---------------- small helpers ----------------
__device__ __forceinline__ float lrelu(float v) { return v > 0.f ? v : 0.2f * v; }
__device__ __forceinline__ float elu1(float v)  { return v > 0.f ? v : (__expf(v) - 1.f); }

// Detect edge_index dtype on device. For genuine int64 data every value is a
// node id in [0, N). For int32 data reinterpreted as int64, values are
// b*2^32 + a and are outside [0, N) unless the high word is 0 (p ~ 1e-5 per
// element; 64 in a row is impossible).
__global__ void k_detect(const void* ei, int N)
{
    if (threadIdx.x == 0 && blockIdx.x == 0) {
        const long long* p = (const long long*)ei;
        int bad = 0;
        for (int i = 0; i < 64; i++) {
            long long v = p[i];
            if (v < 0 || v >= (long long)N) bad = 1;
        }
        g_is32 = bad;
    }
}

__device__ __forceinline__ int edge_at(const void* ei, int idx, int is32)
{
    return is32 ? ((const int*)ei)[idx] : (int)((const long long*)ei)[idx];
}

// ---------------- GEMM1: h1[N,64] = x[N,128] @ W1[128,64], + a_src/a_dst epilogue
__global__ __launch_bounds__(256) void k_gemm1(
    const float* __restrict__ x, const float* __restrict__ W,
    const float* __restrict__ atts, const float* __restrict__ attd, int N)
{
    __shared__ float Ws[32][64];
    __shared__ float xsT[32][132];
    __shared__ float sAs[64], sAd[64];

    int tid = threadIdx.x;
    if (tid < 64) { sAs[tid] = atts[tid]; sAd[tid] = attd[tid]; }

    int rg = tid >> 3;        // 0..31 (row group)
    int cg = tid & 7;         // 0..7  (head / column group)
    int rowBase = blockIdx.x * 128;

    float acc[4][8];
#pragma unroll
    for (int i = 0; i < 4; i++)
#pragma unroll
        for (int c = 0; c < 8; c++) acc[i][c] = 0.f;

    const float4* x4 = (const float4*)x;
    const float4* W4 = (const float4*)W;

    for (int kc = 0; kc < 4; kc++) {
        __syncthreads();
        // W chunk: rows kc*32 .. +32  (32x64 floats = 512 float4)
#pragma unroll
        for (int i = 0; i < 2; i++) {
            int f = tid + i * 256;
            int kk = f >> 4, qj = f & 15;
            ((float4*)&Ws[kk][0])[qj] = W4[(kc * 32 + kk) * 16 + qj];
        }
        // x chunk transposed: xsT[k][r], 128 rows x 32 k
#pragma unroll
        for (int i = 0; i < 4; i++) {
            int f = tid + i * 256;         // 0..1023
            int r = f >> 3, q = f & 7;
            int gr = rowBase + r;
            float4 xv = make_float4(0.f, 0.f, 0.f, 0.f);
            if (gr < N) xv = x4[(size_t)gr * 32 + kc * 8 + q];
            xsT[q * 4 + 0][r] = xv.x;
            xsT[q * 4 + 1][r] = xv.y;
            xsT[q * 4 + 2][r] = xv.z;
            xsT[q * 4 + 3][r] = xv.w;
        }
        __syncthreads();
#pragma unroll
        for (int kk = 0; kk < 32; kk++) {
            float4 xv = *(const float4*)&xsT[kk][rg * 4];
            float4 w0 = *(const float4*)&Ws[kk][cg * 8];
            float4 w1 = *(const float4*)&Ws[kk][cg * 8 + 4];
            float xa[4] = {xv.x, xv.y, xv.z, xv.w};
            float wa[8] = {w0.x, w0.y, w0.z, w0.w, w1.x, w1.y, w1.z, w1.w};
#pragma unroll
            for (int i = 0; i < 4; i++)
#pragma unroll
                for (int c = 0; c < 8; c++) acc[i][c] += xa[i] * wa[c];
        }
    }

    // epilogue: store h1 + per-(row,head) attention dots
#pragma unroll
    for (int i = 0; i < 4; i++) {
        int row = rowBase + rg * 4 + i;
        if (row >= N) continue;
        float4 o0 = make_float4(acc[i][0], acc[i][1], acc[i][2], acc[i][3]);
        float4 o1 = make_float4(acc[i][4], acc[i][5], acc[i][6], acc[i][7]);
        float* hp = g_h1 + (size_t)row * 64 + cg * 8;
        ((float4*)hp)[0] = o0;
        ((float4*)hp)[1] = o1;
        float s = 0.f, d = 0.f;
#pragma unroll
        for (int c = 0; c < 8; c++) {
            s += acc[i][c] * sAs[cg * 8 + c];
            d += acc[i][c] * sAd[cg * 8 + c];
        }
        g_a1s[row * 8 + cg] = s;
        g_a1d[row * 8 + cg] = d;
    }
}

// ---------------- CSR build ----------------
__global__ void k_zero_deg(int N)
{
    int i = blockIdx.x * blockDim.x + threadIdx.x;
    if (i < N) g_deg[i] = 0;
}

__global__ void k_deg(const void* __restrict__ ei, int E, int M)
{
    int i = blockIdx.x * blockDim.x + threadIdx.x;
    if (i >= M) return;
    int is32 = g_is32;
    int d = (i < E) ? edge_at(ei, E + i, is32) : (i - E);
    atomicAdd(&g_deg[d], 1);
}

__global__ __launch_bounds__(1024) void k_bsum(int N)
{
    __shared__ int sm[1024];
    int i = blockIdx.x * 1024 + threadIdx.x;
    sm[threadIdx.x] = (i < N) ? g_deg[i] : 0;
    __syncthreads();
    for (int s = 512; s > 0; s >>= 1) {
        if (threadIdx.x < s) sm[threadIdx.x] += sm[threadIdx.x + s];
        __syncthreads();
    }
    if (threadIdx.x == 0) g_bsum[blockIdx.x] = sm[0];
}

__global__ void k_scanb(int nb, int N, int M)
{
    if (threadIdx.x == 0 && blockIdx.x == 0) {
        int run = 0;
        for (int b = 0; b < nb; b++) { int t = g_bsum[b]; g_bsum[b] = run; run += t; }
        g_row[N] = M;
    }
}

__global__ __launch_bounds__(1024) void k_scan3(int N)
{
    __shared__ int sm[1024];
    int tid = threadIdx.x;
    int i = blockIdx.x * 1024 + tid;
    int v = (i < N) ? g_deg[i] : 0;
    sm[tid] = v;
    __syncthreads();
    for (int off = 1; off < 1024; off <<= 1) {
        int t = (tid >= off) ? sm[tid - off] : 0;
        __syncthreads();
        sm[tid] += t;
        __syncthreads();
    }
    if (i < N) {
        int excl = g_bsum[blockIdx.x] + sm[tid] - v;
        g_row[i] = excl;
        g_cur[i] = excl;
    }
}

__global__ void k_scatter(const void* __restrict__ ei, int E, int M)
{
    int i = blockIdx.x * blockDim.x + threadIdx.x;
    if (i >= M) return;
    int is32 = g_is32;
    int s, d;
    if (i < E) { s = edge_at(ei, i, is32); d = edge_at(ei, E + i, is32); }
    else       { s = d = i - E; }
    int pos = atomicAdd(&g_cur[d], 1);
    g_csr[pos] = s;
}

// ---------------- layer-1 gather: softmax + aggregate + bias + ELU ----------------
__global__ __launch_bounds__(256) void k_gather1(const float* __restrict__ b1, int N)
{
    int t = blockIdx.x * 256 + threadIdx.x;
    int n = t >> 3, h = t & 7;
    if (n >= N) return;
    int beg = g_row[n], end = g_row[n + 1];
    float ad = g_a1d[n * 8 + h];

    float ssum = 0.f;
    for (int e = beg; e < end; e++) {
        int s = g_csr[e];
        float v = lrelu(g_a1s[s * 8 + h] + ad);
        ssum += __expf(v);
    }
    float inv = 1.f / (ssum + 1e-16f);

    float4 A0 = make_float4(0.f, 0.f, 0.f, 0.f), A1 = A0;
    for (int e = beg; e < end; e++) {
        int s = g_csr[e];
        float v = lrelu(g_a1s[s * 8 + h] + ad);
        float al = __expf(v) * inv;
        const float4* hp = (const float4*)(g_h1 + (size_t)s * 64 + h * 8);
        float4 u0 = hp[0], u1 = hp[1];
        A0.x += al * u0.x; A0.y += al * u0.y; A0.z += al * u0.z; A0.w += al * u0.w;
        A1.x += al * u1.x; A1.y += al * u1.y; A1.z += al * u1.z; A1.w += al * u1.w;
    }
    const float4* b4 = (const float4*)b1;
    float4 bb0 = b4[h * 2], bb1 = b4[h * 2 + 1];
    A0.x = elu1(A0.x + bb0.x); A0.y = elu1(A0.y + bb0.y);
    A0.z = elu1(A0.z + bb0.z); A0.w = elu1(A0.w + bb0.w);
    A1.x = elu1(A1.x + bb1.x); A1.y = elu1(A1.y + bb1.y);
    A1.z = elu1(A1.z + bb1.z); A1.w = elu1(A1.w + bb1.w);
    float* op = g_hm + (size_t)n * 64 + h * 8;
    ((float4*)op)[0] = A0;
    ((float4*)op)[1] = A1;
}

// ---------------- GEMM2: h2[N,40] = hm[N,64] @ W2[64,40], + a_src2/a_dst2 ----------------
__global__ __launch_bounds__(256) void k_gemm2(
    const float* __restrict__ W2, const float* __restrict__ as2,
    const float* __restrict__ ad2, int N)
{
    __shared__ float Ws[64][40];
    __shared__ float xsT[16][260];
    __shared__ float sA[40], sD[40];

    int tid = threadIdx.x;
    if (tid < 40) { sA[tid] = as2[tid]; sD[tid] = ad2[tid]; }
    for (int f = tid; f < 640; f += 256)
        ((float4*)&Ws[0][0])[f] = ((const float4*)W2)[f];

    int rg = tid >> 2;   // 0..63
    int cg = tid & 3;    // 0..3 -> cols cg*10..+9
    int rowBase = blockIdx.x * 256;

    float acc[4][10];
#pragma unroll
    for (int i = 0; i < 4; i++)
#pragma unroll
        for (int c = 0; c < 10; c++) acc[i][c] = 0.f;

    const float4* hm4 = (const float4*)g_hm;

    for (int kc = 0; kc < 4; kc++) {
        __syncthreads();
#pragma unroll
        for (int i = 0; i < 4; i++) {
            int f = tid + i * 256;        // 0..1023
            int r = f >> 2, q = f & 3;
            int gr = rowBase + r;
            float4 xv = make_float4(0.f, 0.f, 0.f, 0.f);
            if (gr < N) xv = hm4[(size_t)gr * 16 + kc * 4 + q];
            xsT[q * 4 + 0][r] = xv.x;
            xsT[q * 4 + 1][r] = xv.y;
            xsT[q * 4 + 2][r] = xv.z;
            xsT[q * 4 + 3][r] = xv.w;
        }
        __syncthreads();
#pragma unroll
        for (int kk = 0; kk < 16; kk++) {
            float4 xv = *(const float4*)&xsT[kk][rg * 4];
            float xa[4] = {xv.x, xv.y, xv.z, xv.w};
            float w[10];
#pragma unroll
            for (int c = 0; c < 10; c++) w[c] = Ws[kc * 16 + kk][cg * 10 + c];
#pragma unroll
            for (int i = 0; i < 4; i++)
#pragma unroll
                for (int c = 0; c < 10; c++) acc[i][c] += xa[i] * w[c];
        }
    }

#pragma unroll
    for (int i = 0; i < 4; i++) {
        int row = rowBase + rg * 4 + i;
        float ps = 0.f, pd = 0.f;
#pragma unroll
        for (int c = 0; c < 10; c++) {
            ps += acc[i][c] * sA[cg * 10 + c];
            pd += acc[i][c] * sD[cg * 10 + c];
        }
        ps += __shfl_xor_sync(0xffffffffu, ps, 1);
        ps += __shfl_xor_sync(0xffffffffu, ps, 2);
        pd += __shfl_xor_sync(0xffffffffu, pd, 1);
        pd += __shfl_xor_sync(0xffffffffu, pd, 2);
        if (row < N) {
            float* hp = g_h2 + (size_t)row * 40 + cg * 10;
#pragma unroll
            for (int c = 0; c < 10; c++) hp[c] = acc[i][c];
            if (cg == 0) { g_a2s[row] = ps; g_a2d[row] = pd; }
        }
    }
}

// ---------------- layer-2 gather: softmax + aggregate + bias + log_softmax ----------------
__global__ __launch_bounds__(256) void k_gather2(
    const float* __restrict__ b2, float* __restrict__ out, int N)
{
    int t = blockIdx.x * 256 + threadIdx.x;
    int n = t >> 3, p = t & 7;          // p: 8 lanes per node, 5 classes each
    bool valid = (n < N);
    if (!valid) n = N - 1;              // keep all lanes alive for shfl groups
    int beg = g_row[n], end = g_row[n + 1];
    float ad = g_a2d[n];

    float ssum = 0.f;
    for (int e = beg; e < end; e++) {
        int s = g_csr[e];
        float v = lrelu(g_a2s[s] + ad);
        ssum += __expf(v);
    }
    float inv = 1.f / (ssum + 1e-16f);

    float acc[5] = {0.f, 0.f, 0.f, 0.f, 0.f};
    for (int e = beg; e < end; e++) {
        int s = g_csr[e];
        float v = lrelu(g_a2s[s] + ad);
        float al = __expf(v) * inv;
        const float* hp = g_h2 + (size_t)s * 40 + p * 5;
#pragma unroll
        for (int j = 0; j < 5; j++) acc[j] += al * hp[j];
    }

    float o[5];
    float mx = -1e30f;
#pragma unroll
    for (int j = 0; j < 5; j++) { o[j] = acc[j] + b2[p * 5 + j]; mx = fmaxf(mx, o[j]); }
#pragma unroll
    for (int msk = 1; msk < 8; msk <<= 1)
        mx = fmaxf(mx, __shfl_xor_sync(0xffffffffu, mx, msk));
    float se = 0.f;
#pragma unroll
    for (int j = 0; j < 5; j++) se += __expf(o[j] - mx);
#pragma unroll
    for (int msk = 1; msk < 8; msk <<= 1)
        se += __shfl_xor_sync(0xffffffffu, se, msk);
    float lse = mx + logf(se);

    if (valid) {
        float* op = out + (size_t)n * 40 + p * 5;
#pragma unroll
        for (int j = 0; j < 5; j++) op[j] = o[j] - lse;
    }
}

// ---------------- launch ----------------
extern "C" void kernel_launch(void* const* d_in, const int* in_sizes, int n_in,
                              void* d_out, int out_size)
{
    const float* x    = (const float*)d_in[0];
    const void*  ei   = d_in[1];
    const float* W1   = (const float*)d_in[2];
    const float* as1  = (const float*)d_in[3];
    const float* ad1  = (const float*)d_in[4];
    const float* b1   = (const float*)d_in[5];
    const float* W2   = (const float*)d_in[6];
    const float* as2  = (const float*)d_in[7];
    const float* ad2  = (const float*)d_in[8];
    const float* b2   = (const float*)d_in[9];
    float*       out  = (float*)d_out;

    int N = in_sizes[0] / F_IN;
    int E = in_sizes[1] / 2;
    int M = E + N;
    int NB = (N + 1023) / 1024;

    k_detect<<<1, 32>>>(ei, N);
    k_zero_deg<<<(N + 255) / 256, 256>>>(N);
    k_gemm1<<<(N + 127) / 128, 256>>>(x, W1, as1, ad1, N);
    k_deg<<<(M + 255) / 256, 256>>>(ei, E, M);
    k_bsum<<<NB, 1024>>>(N);
    k_scanb<<<1, 32>>>(NB, N, M);
    k_scan3<<<NB, 1024>>>(N);
    k_scatter<<<(M + 255) / 256, 256>>>(ei, E, M);
    k_gather1<<<(N * 8 + 255) / 256, 256>>>(b1, N);
    k_gemm2<<<(N + 255) / 256, 256>>>(W2, as2, ad2, N);
    k_gather2<<<(N * 8 + 255) / 256, 256>>>(b2, out, N);
}

// round 3
// speedup vs baseline: 1.1562x; 1.1562x over previous
#include <cuda_runtime.h>
#include <stdint.h>

#define F_IN 128
#define D1   64
#define H1   8
#define C2   40
#define NMAX 100352
#define MMAX 1703936   // E + N upper bound

// ---------------- scratch (static device allocations) ----------------
__device__ __align__(16) float g_h1 [NMAX * D1];   // layer1 features h = x@W1
__device__ __align__(16) float g_hm [NMAX * D1];   // elu(agg1)+b1  (layer2 input)
__device__ __align__(16) float g_a1s[NMAX * H1];
__device__ __align__(16) float g_a1d[NMAX * H1];
__device__ __align__(16) float g_h2 [NMAX * C2];
__device__ __align__(16) float g_a2s[NMAX];
__device__ __align__(16) float g_a2d[NMAX];
__device__ __align__(16) int   g_deg[NMAX];
__device__ __align__(16) int   g_cur[NMAX];
__device__ __align__(16) int   g_row[NMAX + 1];
__device__ __align__(16) int   g_bsum[256];
__device__ __align__(16) int   g_csr[MMAX];
__device__ int g_is32;   // 1 if edge_index is int32, 0 if int64

// ---------------- small helpers ----------------
__device__ __forceinline__ float lrelu(float v) { return v > 0.f ? v : 0.2f * v; }
__device__ __forceinline__ float elu1(float v)  { return v > 0.f ? v : (__expf(v) - 1.f); }

__device__ __forceinline__ int edge_at(const void* ei, int idx, int is32)
{
    return is32 ? ((const int*)ei)[idx] : (int)((const long long*)ei)[idx];
}

// ---------------- init: zero degrees + detect edge dtype ----------------
// For genuine int64 data every value is a node id in [0, N). For int32 data
// reinterpreted as int64, values are b*2^32+a, out of range unless the high
// word happens to be 0 (p~1e-5 each; 64 in a row is impossible).
__global__ void k_init(const void* ei, int N)
{
    int i = blockIdx.x * blockDim.x + threadIdx.x;
    if (i < N) g_deg[i] = 0;
    if (i == 0) {
        const long long* p = (const long long*)ei;
        int bad = 0;
#pragma unroll 8
        for (int k = 0; k < 64; k++) {
            long long v = p[k];
            if (v < 0 || v >= (long long)N) bad = 1;
        }
        g_is32 = bad;
    }
}

// ---------------- GEMM1: h1[N,64] = x[N,128] @ W1[128,64], + a_src/a_dst epilogue
__global__ __launch_bounds__(256) void k_gemm1(
    const float* __restrict__ x, const float* __restrict__ W,
    const float* __restrict__ atts, const float* __restrict__ attd, int N)
{
    __shared__ float Ws[32][64];
    __shared__ float xsT[32][132];
    __shared__ float sAs[64], sAd[64];

    int tid = threadIdx.x;
    if (tid < 64) { sAs[tid] = atts[tid]; sAd[tid] = attd[tid]; }

    int rg = tid >> 3;        // 0..31 (row group)
    int cg = tid & 7;         // 0..7  (head / column group)
    int rowBase = blockIdx.x * 128;

    float acc[4][8];
#pragma unroll
    for (int i = 0; i < 4; i++)
#pragma unroll
        for (int c = 0; c < 8; c++) acc[i][c] = 0.f;

    const float4* x4 = (const float4*)x;
    const float4* W4 = (const float4*)W;

    for (int kc = 0; kc < 4; kc++) {
        __syncthreads();
#pragma unroll
        for (int i = 0; i < 2; i++) {
            int f = tid + i * 256;
            int kk = f >> 4, qj = f & 15;
            ((float4*)&Ws[kk][0])[qj] = W4[(kc * 32 + kk) * 16 + qj];
        }
#pragma unroll
        for (int i = 0; i < 4; i++) {
            int f = tid + i * 256;         // 0..1023
            int r = f >> 3, q = f & 7;
            int gr = rowBase + r;
            float4 xv = make_float4(0.f, 0.f, 0.f, 0.f);
            if (gr < N) xv = x4[(size_t)gr * 32 + kc * 8 + q];
            xsT[q * 4 + 0][r] = xv.x;
            xsT[q * 4 + 1][r] = xv.y;
            xsT[q * 4 + 2][r] = xv.z;
            xsT[q * 4 + 3][r] = xv.w;
        }
        __syncthreads();
#pragma unroll
        for (int kk = 0; kk < 32; kk++) {
            float4 xv = *(const float4*)&xsT[kk][rg * 4];
            float4 w0 = *(const float4*)&Ws[kk][cg * 8];
            float4 w1 = *(const float4*)&Ws[kk][cg * 8 + 4];
            float xa[4] = {xv.x, xv.y, xv.z, xv.w};
            float wa[8] = {w0.x, w0.y, w0.z, w0.w, w1.x, w1.y, w1.z, w1.w};
#pragma unroll
            for (int i = 0; i < 4; i++)
#pragma unroll
                for (int c = 0; c < 8; c++) acc[i][c] += xa[i] * wa[c];
        }
    }

#pragma unroll
    for (int i = 0; i < 4; i++) {
        int row = rowBase + rg * 4 + i;
        if (row >= N) continue;
        float4 o0 = make_float4(acc[i][0], acc[i][1], acc[i][2], acc[i][3]);
        float4 o1 = make_float4(acc[i][4], acc[i][5], acc[i][6], acc[i][7]);
        float* hp = g_h1 + (size_t)row * 64 + cg * 8;
        ((float4*)hp)[0] = o0;
        ((float4*)hp)[1] = o1;
        float s = 0.f, d = 0.f;
#pragma unroll
        for (int c = 0; c < 8; c++) {
            s += acc[i][c] * sAs[cg * 8 + c];
            d += acc[i][c] * sAd[cg * 8 + c];
        }
        g_a1s[row * 8 + cg] = s;
        g_a1d[row * 8 + cg] = d;
    }
}

// ---------------- CSR build ----------------
__global__ void k_deg(const void* __restrict__ ei, int E, int M)
{
    int i = blockIdx.x * blockDim.x + threadIdx.x;
    if (i >= M) return;
    int is32 = g_is32;
    int d = (i < E) ? edge_at(ei, E + i, is32) : (i - E);
    atomicAdd(&g_deg[d], 1);
}

__global__ __launch_bounds__(1024) void k_bsum(int N)
{
    __shared__ int sm[1024];
    int i = blockIdx.x * 1024 + threadIdx.x;
    sm[threadIdx.x] = (i < N) ? g_deg[i] : 0;
    __syncthreads();
    for (int s = 512; s > 0; s >>= 1) {
        if (threadIdx.x < s) sm[threadIdx.x] += sm[threadIdx.x + s];
        __syncthreads();
    }
    if (threadIdx.x == 0) g_bsum[blockIdx.x] = sm[0];
}

// scan within block + block offset from g_bsum (nb <= 128)
__global__ __launch_bounds__(1024) void k_scan3(int N, int M)
{
    __shared__ int sm[1024];
    __shared__ int ws[4];
    __shared__ int s_off;
    int tid = threadIdx.x;
    int bid = blockIdx.x;

    // block offset = sum of g_bsum[0..bid-1]
    if (tid < 128) {
        int v2 = (tid < bid) ? g_bsum[tid] : 0;
#pragma unroll
        for (int m = 16; m > 0; m >>= 1)
            v2 += __shfl_xor_sync(0xffffffffu, v2, m);
        if ((tid & 31) == 0) ws[tid >> 5] = v2;
    }
    __syncthreads();
    if (tid == 0) s_off = ws[0] + ws[1] + ws[2] + ws[3];

    int i = bid * 1024 + tid;
    int v = (i < N) ? g_deg[i] : 0;
    sm[tid] = v;
    __syncthreads();
    for (int off = 1; off < 1024; off <<= 1) {
        int t = (tid >= off) ? sm[tid - off] : 0;
        __syncthreads();
        sm[tid] += t;
        __syncthreads();
    }
    if (i < N) {
        int excl = s_off + sm[tid] - v;
        g_row[i] = excl;
        g_cur[i] = excl;
    }
    if (bid == gridDim.x - 1 && tid == 0) g_row[N] = M;
}

__global__ void k_scatter(const void* __restrict__ ei, int E, int M)
{
    int i = blockIdx.x * blockDim.x + threadIdx.x;
    if (i >= M) return;
    int is32 = g_is32;
    int s, d;
    if (i < E) { s = edge_at(ei, i, is32); d = edge_at(ei, E + i, is32); }
    else       { s = d = i - E; }
    int pos = atomicAdd(&g_cur[d], 1);
    g_csr[pos] = s;
}

// ---------------- layer-1 gather: single-pass softmax+aggregate+bias+ELU ----
__global__ __launch_bounds__(256) void k_gather1(const float* __restrict__ b1, int N)
{
    int t = blockIdx.x * 256 + threadIdx.x;
    int n = t >> 3, h = t & 7;
    if (n >= N) return;
    int beg = g_row[n], end = g_row[n + 1];
    float ad = g_a1d[n * 8 + h];

    float ssum = 0.f;
    float4 A0 = make_float4(0.f, 0.f, 0.f, 0.f), A1 = A0;
    for (int e = beg; e < end; e++) {
        int s = g_csr[e];
        float w = __expf(lrelu(g_a1s[s * 8 + h] + ad));
        ssum += w;
        const float4* hp = (const float4*)(g_h1 + (size_t)s * 64 + h * 8);
        float4 u0 = hp[0], u1 = hp[1];
        A0.x += w * u0.x; A0.y += w * u0.y; A0.z += w * u0.z; A0.w += w * u0.w;
        A1.x += w * u1.x; A1.y += w * u1.y; A1.z += w * u1.z; A1.w += w * u1.w;
    }
    float inv = 1.f / (ssum + 1e-16f);
    const float4* b4 = (const float4*)b1;
    float4 bb0 = b4[h * 2], bb1 = b4[h * 2 + 1];
    A0.x = elu1(A0.x * inv + bb0.x); A0.y = elu1(A0.y * inv + bb0.y);
    A0.z = elu1(A0.z * inv + bb0.z); A0.w = elu1(A0.w * inv + bb0.w);
    A1.x = elu1(A1.x * inv + bb1.x); A1.y = elu1(A1.y * inv + bb1.y);
    A1.z = elu1(A1.z * inv + bb1.z); A1.w = elu1(A1.w * inv + bb1.w);
    float* op = g_hm + (size_t)n * 64 + h * 8;
    ((float4*)op)[0] = A0;
    ((float4*)op)[1] = A1;
}

// ---------------- GEMM2: h2[N,40] = hm[N,64] @ W2[64,40], + a_src2/a_dst2 ----
__global__ __launch_bounds__(256) void k_gemm2(
    const float* __restrict__ W2, const float* __restrict__ as2,
    const float* __restrict__ ad2, int N)
{
    __shared__ float Ws[64][40];
    __shared__ float xsT[16][260];
    __shared__ float sA[40], sD[40];

    int tid = threadIdx.x;
    if (tid < 40) { sA[tid] = as2[tid]; sD[tid] = ad2[tid]; }
    for (int f = tid; f < 640; f += 256)
        ((float4*)&Ws[0][0])[f] = ((const float4*)W2)[f];

    int rg = tid >> 2;   // 0..63
    int cg = tid & 3;    // 0..3 -> cols cg*10..+9
    int rowBase = blockIdx.x * 256;

    float acc[4][10];
#pragma unroll
    for (int i = 0; i < 4; i++)
#pragma unroll
        for (int c = 0; c < 10; c++) acc[i][c] = 0.f;

    const float4* hm4 = (const float4*)g_hm;

    for (int kc = 0; kc < 4; kc++) {
        __syncthreads();
#pragma unroll
        for (int i = 0; i < 4; i++) {
            int f = tid + i * 256;        // 0..1023
            int r = f >> 2, q = f & 3;
            int gr = rowBase + r;
            float4 xv = make_float4(0.f, 0.f, 0.f, 0.f);
            if (gr < N) xv = hm4[(size_t)gr * 16 + kc * 4 + q];
            xsT[q * 4 + 0][r] = xv.x;
            xsT[q * 4 + 1][r] = xv.y;
            xsT[q * 4 + 2][r] = xv.z;
            xsT[q * 4 + 3][r] = xv.w;
        }
        __syncthreads();
#pragma unroll
        for (int kk = 0; kk < 16; kk++) {
            float4 xv = *(const float4*)&xsT[kk][rg * 4];
            float xa[4] = {xv.x, xv.y, xv.z, xv.w};
            float w[10];
#pragma unroll
            for (int c = 0; c < 10; c++) w[c] = Ws[kc * 16 + kk][cg * 10 + c];
#pragma unroll
            for (int i = 0; i < 4; i++)
#pragma unroll
                for (int c = 0; c < 10; c++) acc[i][c] += xa[i] * w[c];
        }
    }

#pragma unroll
    for (int i = 0; i < 4; i++) {
        int row = rowBase + rg * 4 + i;
        float ps = 0.f, pd = 0.f;
#pragma unroll
        for (int c = 0; c < 10; c++) {
            ps += acc[i][c] * sA[cg * 10 + c];
            pd += acc[i][c] * sD[cg * 10 + c];
        }
        ps += __shfl_xor_sync(0xffffffffu, ps, 1);
        ps += __shfl_xor_sync(0xffffffffu, ps, 2);
        pd += __shfl_xor_sync(0xffffffffu, pd, 1);
        pd += __shfl_xor_sync(0xffffffffu, pd, 2);
        if (row < N) {
            float* hp = g_h2 + (size_t)row * 40 + cg * 10;
#pragma unroll
            for (int c = 0; c < 10; c++) hp[c] = acc[i][c];
            if (cg == 0) { g_a2s[row] = ps; g_a2d[row] = pd; }
        }
    }
}

// ---------------- layer-2 gather: single-pass + bias + log_softmax ----------
__global__ __launch_bounds__(256) void k_gather2(
    const float* __restrict__ b2, float* __restrict__ out, int N)
{
    int t = blockIdx.x * 256 + threadIdx.x;
    int n = t >> 3, p = t & 7;          // p: 8 lanes per node, 5 classes each
    bool valid = (n < N);
    if (!valid) n = N - 1;              // keep all lanes alive for shfl groups
    int beg = g_row[n], end = g_row[n + 1];
    float ad = g_a2d[n];

    float ssum = 0.f;
    float acc[5] = {0.f, 0.f, 0.f, 0.f, 0.f};
    for (int e = beg; e < end; e++) {
        int s = g_csr[e];
        float w = __expf(lrelu(g_a2s[s] + ad));
        ssum += w;
        const float* hp = g_h2 + (size_t)s * 40 + p * 5;
#pragma unroll
        for (int j = 0; j < 5; j++) acc[j] += w * hp[j];
    }
    float inv = 1.f / (ssum + 1e-16f);

    float o[5];
    float mx = -1e30f;
#pragma unroll
    for (int j = 0; j < 5; j++) { o[j] = acc[j] * inv + b2[p * 5 + j]; mx = fmaxf(mx, o[j]); }
#pragma unroll
    for (int msk = 1; msk < 8; msk <<= 1)
        mx = fmaxf(mx, __shfl_xor_sync(0xffffffffu, mx, msk));
    float se = 0.f;
#pragma unroll
    for (int j = 0; j < 5; j++) se += __expf(o[j] - mx);
#pragma unroll
    for (int msk = 1; msk < 8; msk <<= 1)
        se += __shfl_xor_sync(0xffffffffu, se, msk);
    float lse = mx + logf(se);

    if (valid) {
        float* op = out + (size_t)n * 40 + p * 5;
#pragma unroll
        for (int j = 0; j < 5; j++) op[j] = o[j] - lse;
    }
}

// ---------------- launch ----------------
extern "C" void kernel_launch(void* const* d_in, const int* in_sizes, int n_in,
                              void* d_out, int out_size)
{
    const float* x    = (const float*)d_in[0];
    const void*  ei   = d_in[1];
    const float* W1   = (const float*)d_in[2];
    const float* as1  = (const float*)d_in[3];
    const float* ad1  = (const float*)d_in[4];
    const float* b1   = (const float*)d_in[5];
    const float* W2   = (const float*)d_in[6];
    const float* as2  = (const float*)d_in[7];
    const float* ad2  = (const float*)d_in[8];
    const float* b2   = (const float*)d_in[9];
    float*       out  = (float*)d_out;

    int N = in_sizes[0] / F_IN;
    int E = in_sizes[1] / 2;
    int M = E + N;
    int NB = (N + 1023) / 1024;

    // lazy one-time resources (host-side only; created on the eager
    // correctness call, before graph capture begins)
    static cudaStream_t s_side = nullptr;
    static cudaEvent_t  ev_fork = nullptr, ev_join = nullptr;
    if (!s_side) {
        cudaStreamCreateWithFlags(&s_side, cudaStreamNonBlocking);
        cudaEventCreateWithFlags(&ev_fork, cudaEventDisableTiming);
        cudaEventCreateWithFlags(&ev_join, cudaEventDisableTiming);
    }

    // fork: gemm1 runs on the side stream, concurrent with CSR build
    cudaEventRecord(ev_fork, 0);
    cudaStreamWaitEvent(s_side, ev_fork, 0);
    k_gemm1<<<(N + 127) / 128, 256, 0, s_side>>>(x, W1, as1, ad1, N);
    cudaEventRecord(ev_join, s_side);

    // main chain: CSR build
    k_init<<<(N + 255) / 256, 256>>>(ei, N);
    k_deg<<<(M + 255) / 256, 256>>>(ei, E, M);
    k_bsum<<<NB, 1024>>>(N);
    k_scan3<<<NB, 1024>>>(N, M);
    k_scatter<<<(M + 255) / 256, 256>>>(ei, E, M);

    // join, then attention layers
    cudaStreamWaitEvent(0, ev_join, 0);
    k_gather1<<<(N * 8 + 255) / 256, 256>>>(b1, N);
    k_gemm2<<<(N + 255) / 256, 256>>>(W2, as2, ad2, N);
    k_gather2<<<(N * 8 + 255) / 256, 256>>>(b2, out, N);
}